// round 15
// baseline (speedup 1.0000x reference)
#include <cuda_runtime.h>
#include <cuda_bf16.h>

static constexpr int BS = 32;
static constexpr int S  = 2048;
static constexpr int H  = 1024;

// Device scratch (no allocs allowed).
__device__ float        g_v[BS * H];   // v[b,h] = hidden[b] @ W (memset each run)
__device__ unsigned int g_cnt[BS];     // per-batch block-completion counters.
                                       // Zero-init at load; the LAST scores
                                       // block of each batch resets its counter
                                       // to 0, so every graph replay starts
                                       // from 0 without a memset node.

// ---------------------------------------------------------------------------
// Stage 1: v[b,h] = sum_k hidden[b,k] * W[k,h]
// R7/R9-proven shape: grid (H/128, BS/8, K/64) = 512 blocks, 128 threads.
// (Every attempt to restructure this kernel — fewer/fatter blocks, float4 W,
// STG partials + reduce — regressed. Block-level parallelism wins here.)
// PDL trigger early so the scores grid pre-launches.
// ---------------------------------------------------------------------------
__global__ void __launch_bounds__(128) v_kernel(const float* __restrict__ hidden,
                                                const float* __restrict__ W) {
    cudaTriggerProgrammaticLaunchCompletion();

    __shared__ float sh[8][64];
    const int h  = blockIdx.x * 128 + threadIdx.x;
    const int b0 = blockIdx.y * 8;
    const int k0 = blockIdx.z * 64;

#pragma unroll
    for (int i = threadIdx.x; i < 8 * 64; i += 128) {
        int bb = i >> 6, kk = i & 63;
        sh[bb][kk] = hidden[(b0 + bb) * H + (k0 + kk)];
    }
    __syncthreads();

    float acc[8];
#pragma unroll
    for (int bb = 0; bb < 8; bb++) acc[bb] = 0.0f;

#pragma unroll 16
    for (int kk = 0; kk < 64; kk++) {
        float w = W[(size_t)(k0 + kk) * H + h];   // coalesced across threads (h)
#pragma unroll
        for (int bb = 0; bb < 8; bb++)
            acc[bb] = fmaf(sh[bb][kk], w, acc[bb]);  // smem broadcast
    }

#pragma unroll
    for (int bb = 0; bb < 8; bb++)
        atomicAdd(&g_v[(b0 + bb) * H + h], acc[bb]);
}

// ---------------------------------------------------------------------------
// Stage 2 (+fused softmax): scores[b,s] = dot(enc[b,s,:], v[b,:]).
// Body identical to the proven R9 kernel: 256-thr blocks, one warp per (b,s),
// 8 rows/block, v[b] staged in 4 KB smem, enc via __ldcs (268 MB single-use).
// NEW: after storing its 8 scores, each block fences + bumps g_cnt[b]; the
// 256th (last) block for batch b runs that row's softmax inline. The scores
// are L2-hot (just written through L2), and per-batch softmax overlaps the
// remaining batches' HBM streaming — the separate softmax kernel (a ~4 us
// all-blocks-complete tail) disappears.
// (Bias term c[b] is constant over s -> cancels in softmax; never computed.)
// ---------------------------------------------------------------------------
__global__ void __launch_bounds__(256) scores_kernel(const float* __restrict__ enc,
                                                     float* __restrict__ out) {
    __shared__ float4 shv[H / 4];  // 4 KB: v[b]
    __shared__ float  red[8];
    __shared__ int    s_last;
    const int warp = threadIdx.x >> 5;
    const int lane = threadIdx.x & 31;
    const int b = blockIdx.x >> 8;                  // 256 blocks per batch
    const int s = ((blockIdx.x & 255) << 3) + warp; // 8 rows per block

    cudaGridDependencySynchronize();                // wait: g_v complete
    cudaTriggerProgrammaticLaunchCompletion();

    const float4* vg = (const float4*)(g_v + b * H);
    for (int i = threadIdx.x; i < H / 4; i += 256) shv[i] = vg[i];
    __syncthreads();

    const float4* e = (const float4*)(enc + ((size_t)b * S + s) * H);

    float a0 = 0.f, a1 = 0.f;
#pragma unroll
    for (int i = 0; i < 8; i++) {
        float4 x = __ldcs(e + lane + 32 * i);
        float4 v = shv[lane + 32 * i];
        a0 = fmaf(x.x, v.x, a0);
        a1 = fmaf(x.y, v.y, a1);
        a0 = fmaf(x.z, v.z, a0);
        a1 = fmaf(x.w, v.w, a1);
    }
    float acc = a0 + a1;
#pragma unroll
    for (int off = 16; off; off >>= 1)
        acc += __shfl_xor_sync(0xffffffffu, acc, off);
    if (lane == 0) {
        out[b * S + s] = acc;
        __threadfence();           // publish this warp's score device-wide
    }
    __syncthreads();

    if (threadIdx.x == 0)
        s_last = (atomicAdd(&g_cnt[b], 1u) == 255u);
    __syncthreads();
    if (!s_last) return;

    // ---- Last block for batch b: row softmax over S=2048 (L2-hot). ----
    const int tid = threadIdx.x;
    float4* row = (float4*)(out + b * S);          // 512 float4 per row

    // __ldcg: read through L2 (bypass any L1 state; acquire side of the
    // fence/atomic handshake).
    float4 v0 = __ldcg(row + tid);
    float4 v1 = __ldcg(row + tid + 256);
    float m = fmaxf(fmaxf(fmaxf(v0.x, v0.y), fmaxf(v0.z, v0.w)),
                    fmaxf(fmaxf(v1.x, v1.y), fmaxf(v1.z, v1.w)));
#pragma unroll
    for (int off = 16; off; off >>= 1)
        m = fmaxf(m, __shfl_xor_sync(0xffffffffu, m, off));
    if (lane == 0) red[warp] = m;
    __syncthreads();
    float M = red[0];
#pragma unroll
    for (int w = 1; w < 8; w++) M = fmaxf(M, red[w]);

    v0.x = __expf(v0.x - M); v0.y = __expf(v0.y - M);
    v0.z = __expf(v0.z - M); v0.w = __expf(v0.w - M);
    v1.x = __expf(v1.x - M); v1.y = __expf(v1.y - M);
    v1.z = __expf(v1.z - M); v1.w = __expf(v1.w - M);
    float sum = (v0.x + v0.y) + (v0.z + v0.w) + (v1.x + v1.y) + (v1.z + v1.w);
#pragma unroll
    for (int off = 16; off; off >>= 1)
        sum += __shfl_xor_sync(0xffffffffu, sum, off);
    __syncthreads();               // red[] reuse hazard
    if (lane == 0) red[warp] = sum;
    __syncthreads();
    float T = 0.f;
#pragma unroll
    for (int w = 0; w < 8; w++) T += red[w];
    const float inv = 1.0f / T;

    v0.x *= inv; v0.y *= inv; v0.z *= inv; v0.w *= inv;
    v1.x *= inv; v1.y *= inv; v1.z *= inv; v1.w *= inv;
    row[tid]       = v0;
    row[tid + 256] = v1;

    if (tid == 0) g_cnt[b] = 0;    // self-reset for the next graph replay
}

// ---------------------------------------------------------------------------
extern "C" void kernel_launch(void* const* d_in, const int* in_sizes, int n_in,
                              void* d_out, int out_size) {
    // Identify inputs by element count (all four sizes are distinct).
    const float* hidden = nullptr;  // 32768
    const float* enc    = nullptr;  // 67108864
    const float* W      = nullptr;  // 1048576
    for (int i = 0; i < n_in; i++) {
        long sz = in_sizes[i];
        if      (sz == (long)BS * S * H) enc    = (const float*)d_in[i];
        else if (sz == (long)H * H)      W      = (const float*)d_in[i];
        else if (sz == (long)BS * H)     hidden = (const float*)d_in[i];
        // bias (H) intentionally unused: softmax-invariant per-row constant
    }
    float* out = (float*)d_out;  // [BS, S] fp32

    // Stage 0: zero g_v via a captured memset node (no kernel launch).
    void* vptr = nullptr;
    cudaGetSymbolAddress(&vptr, g_v);
    cudaMemsetAsync(vptr, 0, sizeof(float) * BS * H, 0);

    // Stage 1: plain launch (full dependency on the memset node).
    v_kernel<<<dim3(H / 128, BS / 8, 16), 128>>>(hidden, W);

    // Stage 2 (+fused softmax): PDL launch — pre-launches during v_kernel;
    // gridDependencySynchronize provides the data-ordering barrier.
    cudaLaunchAttribute attrs[1];
    attrs[0].id = cudaLaunchAttributeProgrammaticStreamSerialization;
    attrs[0].val.programmaticStreamSerializationAllowed = 1;

    cudaLaunchConfig_t cfg = {};
    cfg.gridDim  = dim3((BS * S) / 8);
    cfg.blockDim = dim3(256);
    cfg.stream   = 0;
    cfg.attrs    = attrs;
    cfg.numAttrs = 1;
    cudaLaunchKernelEx(&cfg, scores_kernel, enc, out);
}

// round 17
// speedup vs baseline: 1.3979x; 1.3979x over previous
#include <cuda_runtime.h>
#include <cuda_bf16.h>

static constexpr int BS = 32;
static constexpr int S  = 2048;
static constexpr int H  = 1024;

// Scratch for v[b,h] = hidden[b] @ W  (device global: no allocs allowed).
// Zeroed each launch via a captured cudaMemsetAsync node.
__device__ float g_v[BS * H];

// ---------------------------------------------------------------------------
// Stage 1: v[b,h] = sum_k hidden[b,k] * W[k,h]
// Evidence across R7-R12: v duration is monotone decreasing in block count
// (128 blks -> 19.7us, 256 -> 14.4, 512 -> 11.9). Extrapolate: 1024 blocks
// via 4-batch groups. grid (H/128, BS/4, K/64) = (8, 8, 16), 128 threads.
// Per-thread: one h column, 4 batches, 64 k, unroll-16 (~16 W loads in
// flight). ~28 warps/SM. Atomic count unchanged (512K, spread addresses).
// W L2 re-reads double to 32MB — far below the LTS cap, harmless.
// PDL trigger early so the scores grid pre-launches.
// ---------------------------------------------------------------------------
__global__ void __launch_bounds__(128) v_kernel(const float* __restrict__ hidden,
                                                const float* __restrict__ W) {
    cudaTriggerProgrammaticLaunchCompletion();

    __shared__ float sh[4][64];
    const int h  = blockIdx.x * 128 + threadIdx.x;
    const int b0 = blockIdx.y * 4;
    const int k0 = blockIdx.z * 64;

#pragma unroll
    for (int i = threadIdx.x; i < 4 * 64; i += 128) {
        int bb = i >> 6, kk = i & 63;
        sh[bb][kk] = hidden[(b0 + bb) * H + (k0 + kk)];
    }
    __syncthreads();

    float acc[4];
#pragma unroll
    for (int bb = 0; bb < 4; bb++) acc[bb] = 0.0f;

#pragma unroll 16
    for (int kk = 0; kk < 64; kk++) {
        float w = W[(size_t)(k0 + kk) * H + h];   // coalesced across threads (h)
#pragma unroll
        for (int bb = 0; bb < 4; bb++)
            acc[bb] = fmaf(sh[bb][kk], w, acc[bb]);  // smem broadcast
    }

#pragma unroll
    for (int bb = 0; bb < 4; bb++)
        atomicAdd(&g_v[(b0 + bb) * H + h], acc[bb]);
}

// ---------------------------------------------------------------------------
// Stage 2: scores[b,s] = dot(enc[b,s,:], v[b,:])   -- the HBM-bound stage.
// EXACT R9 winner: 256-thr blocks, one warp per (b,s), 8 rows/block, v[b]
// staged in 4 KB smem, enc via __ldcs (268 MB single-use, evict-streaming),
// 8 LDG.128 in flight per lane. No fences, no counters — every added sync
// (R13) slowed the stream. PDL: GDS before any g_v use; trigger lets the
// softmax grid pre-launch and park.
// ---------------------------------------------------------------------------
__global__ void __launch_bounds__(256) scores_kernel(const float* __restrict__ enc,
                                                     float* __restrict__ out) {
    __shared__ float4 shv[H / 4];  // 4 KB: v[b]
    const int warp = threadIdx.x >> 5;
    const int lane = threadIdx.x & 31;
    const int b = blockIdx.x >> 8;                  // 256 blocks per batch
    const int s = ((blockIdx.x & 255) << 3) + warp; // 8 rows per block

    cudaGridDependencySynchronize();                // wait: g_v complete
    cudaTriggerProgrammaticLaunchCompletion();      // allow softmax pre-launch

    const float4* vg = (const float4*)(g_v + b * H);
    for (int i = threadIdx.x; i < H / 4; i += 256) shv[i] = vg[i];
    __syncthreads();

    const float4* e = (const float4*)(enc + ((size_t)b * S + s) * H);

    float a0 = 0.f, a1 = 0.f;
#pragma unroll
    for (int i = 0; i < 8; i++) {
        float4 x = __ldcs(e + lane + 32 * i);
        float4 v = shv[lane + 32 * i];
        a0 = fmaf(x.x, v.x, a0);
        a1 = fmaf(x.y, v.y, a1);
        a0 = fmaf(x.z, v.z, a0);
        a1 = fmaf(x.w, v.w, a1);
    }
    float acc = a0 + a1;
#pragma unroll
    for (int off = 16; off; off >>= 1)
        acc += __shfl_xor_sync(0xffffffffu, acc, off);
    if (lane == 0) out[b * S + s] = acc;
}

// ---------------------------------------------------------------------------
// Stage 3: in-place row softmax over S=2048. EXACT R9 winner (32x256 scalar).
// PDL: blocks pre-launch during scores' execution, park at GDS, then run
// with the launch ramp already paid.
// (Bias term c[b] is constant over s -> cancels in softmax; never computed.)
// ---------------------------------------------------------------------------
__global__ void __launch_bounds__(256) softmax_kernel(float* __restrict__ out) {
    const int b    = blockIdx.x;
    const int tid  = threadIdx.x;
    const int warp = tid >> 5, lane = tid & 31;
    float* row = out + b * S;
    __shared__ float red[8];

    cudaGridDependencySynchronize();                // wait: scores complete

    float v[8];
    float m = -1e30f;
#pragma unroll
    for (int i = 0; i < 8; i++) {
        v[i] = row[tid + 256 * i];
        m = fmaxf(m, v[i]);
    }
#pragma unroll
    for (int off = 16; off; off >>= 1)
        m = fmaxf(m, __shfl_xor_sync(0xffffffffu, m, off));
    if (lane == 0) red[warp] = m;
    __syncthreads();
    float M = red[0];
#pragma unroll
    for (int w = 1; w < 8; w++) M = fmaxf(M, red[w]);

    float sum = 0.f;
#pragma unroll
    for (int i = 0; i < 8; i++) {
        v[i] = __expf(v[i] - M);
        sum += v[i];
    }
#pragma unroll
    for (int off = 16; off; off >>= 1)
        sum += __shfl_xor_sync(0xffffffffu, sum, off);
    __syncthreads();               // red[] reuse hazard
    if (lane == 0) red[warp] = sum;
    __syncthreads();
    float T = 0.f;
#pragma unroll
    for (int w = 0; w < 8; w++) T += red[w];
    float inv = 1.0f / T;
#pragma unroll
    for (int i = 0; i < 8; i++)
        row[tid + 256 * i] = v[i] * inv;
}

// ---------------------------------------------------------------------------
extern "C" void kernel_launch(void* const* d_in, const int* in_sizes, int n_in,
                              void* d_out, int out_size) {
    // Identify inputs by element count (all four sizes are distinct).
    const float* hidden = nullptr;  // 32768
    const float* enc    = nullptr;  // 67108864
    const float* W      = nullptr;  // 1048576
    for (int i = 0; i < n_in; i++) {
        long sz = in_sizes[i];
        if      (sz == (long)BS * S * H) enc    = (const float*)d_in[i];
        else if (sz == (long)H * H)      W      = (const float*)d_in[i];
        else if (sz == (long)BS * H)     hidden = (const float*)d_in[i];
        // bias (H) intentionally unused: softmax-invariant per-row constant
    }
    float* out = (float*)d_out;  // [BS, S] fp32

    // Stage 0: zero g_v via a captured memset node (no kernel launch).
    void* vptr = nullptr;
    cudaGetSymbolAddress(&vptr, g_v);
    cudaMemsetAsync(vptr, 0, sizeof(float) * BS * H, 0);

    // Stage 1: plain launch (full dependency on the memset node).
    v_kernel<<<dim3(H / 128, BS / 4, 16), 128>>>(hidden, W);

    // Stages 2+3: PDL launches — each kernel's launch/ramp overlaps its
    // predecessor's execution; device-side gridDependencySynchronize provides
    // the data-ordering barrier.
    cudaLaunchAttribute attrs[1];
    attrs[0].id = cudaLaunchAttributeProgrammaticStreamSerialization;
    attrs[0].val.programmaticStreamSerializationAllowed = 1;

    {
        cudaLaunchConfig_t cfg = {};
        cfg.gridDim  = dim3((BS * S) / 8);
        cfg.blockDim = dim3(256);
        cfg.stream   = 0;
        cfg.attrs    = attrs;
        cfg.numAttrs = 1;
        cudaLaunchKernelEx(&cfg, scores_kernel, enc, out);
    }
    {
        cudaLaunchConfig_t cfg = {};
        cfg.gridDim  = dim3(BS);
        cfg.blockDim = dim3(256);
        cfg.stream   = 0;
        cfg.attrs    = attrs;
        cfg.numAttrs = 1;
        cudaLaunchKernelEx(&cfg, softmax_kernel, out);
    }
}